// round 14
// baseline (speedup 1.0000x reference)
#include <cuda_runtime.h>
#include <cuda_fp16.h>
#include <cstdint>
#include <cstddef>

#define NSAMP 16384
#define HID   512
#define DIN   128
#define EOBS  4096
#define KOBS  40
#define DTF   0.05f

#define MODE_RELU_G  2
#define MODE_RNN     3
#define MODE_LOSS    5
#define MODE_ZSTEP   6
#define MODE_HEULER  7
#define MODE_ZNEW    8
#define MODE_STOREH  9

// ------------------------------------------------------------------
// Device scratch (no allocations allowed)
// ------------------------------------------------------------------
__device__ __half g_h_hi[(size_t)NSAMP*HID];
__device__ __half g_h_lo[(size_t)NSAMP*HID];
__device__ __half g_z_hi[(size_t)NSAMP*HID];
__device__ __half g_z_lo[(size_t)NSAMP*HID];
__device__ __half g_u  [(size_t)NSAMP*HID];   // u0 = tanh(z)
__device__ __half g_v  [(size_t)NSAMP*HID];   // v = u0 + u1
__device__ __half g_p1_hi[(size_t)EOBS*HID];
__device__ __half g_hn_hi[(size_t)EOBS*HID];
__device__ __half g_hn_lo[(size_t)EOBS*HID];
__device__ __half g_X_hi[(size_t)KOBS*EOBS*DIN];

__device__ __half g_Wih_h[HID*DIN];
__device__ __half g_Whh_h[HID*HID];
__device__ __half g_Wo1_h[HID*HID];
__device__ __half g_Wo2_h[HID*HID];
__device__ __half g_Wo2T_h[HID*HID];   // Wo2 transposed (for W21 build)
__device__ __half g_W21_h[HID*HID];    // Wo1 @ Wo2
__device__ __half g_Wp1_h[HID*HID];
__device__ __half g_Wp2_h[DIN*HID];
__device__ float  g_cvec[HID];         // bo2 @ Wo1^T
__device__ __half g_zch[HID], g_zcl[HID], g_uc[HID];  // init column values

__device__ double g_loss;
__device__ double g_totm;

// ------------------------------------------------------------------
// PTX helpers (portable sm_80+)
// ------------------------------------------------------------------
__device__ __forceinline__ uint32_t smem_u32(const void* p) {
    uint32_t a;
    asm("{ .reg .u64 t; cvta.to.shared.u64 t, %1; cvt.u32.u64 %0, t; }" : "=r"(a) : "l"(p));
    return a;
}
__device__ __forceinline__ void cp16(uint32_t dst, const void* src) {
    asm volatile("cp.async.cg.shared.global [%0], [%1], 16;" :: "r"(dst), "l"(src) : "memory");
}
__device__ __forceinline__ void cp_commit() {
    asm volatile("cp.async.commit_group;" ::: "memory");
}
template<int N>
__device__ __forceinline__ void cp_wait() {
    asm volatile("cp.async.wait_group %0;" :: "n"(N) : "memory");
}
__device__ __forceinline__ void ldm4(uint32_t* r, uint32_t addr) {
    asm volatile("ldmatrix.sync.aligned.m8n8.x4.shared.b16 {%0,%1,%2,%3}, [%4];"
                 : "=r"(r[0]), "=r"(r[1]), "=r"(r[2]), "=r"(r[3]) : "r"(addr));
}
__device__ __forceinline__ void mma16816(float* d, const uint32_t* a, const uint32_t* b) {
    asm volatile(
        "mma.sync.aligned.m16n8k16.row.col.f32.f16.f16.f32 "
        "{%0,%1,%2,%3}, {%4,%5,%6,%7}, {%8,%9}, {%0,%1,%2,%3};"
        : "+f"(d[0]), "+f"(d[1]), "+f"(d[2]), "+f"(d[3])
        : "r"(a[0]), "r"(a[1]), "r"(a[2]), "r"(a[3]), "r"(b[0]), "r"(b[1]));
}
__device__ __forceinline__ uint32_t sw128(uint32_t off) { return off ^ ((off >> 3) & 0x70); }

#define TILE_BYTES   16384
#define STAGE_BYTES  32768
#define NSTAGE       3
#define SMEM_DYN     (NSTAGE*STAGE_BYTES + 1024 + 1024)

// ------------------------------------------------------------------
// GEMM body: C[M,NOUT] = epi( A[M,K] @ W[NOUT,K]^T )   [R12 core, proven]
// ------------------------------------------------------------------
template<int MODE, int KDIM, int NOUT>
__device__ __forceinline__
void gemm_body(const __half* __restrict__ Ah,  const __half* __restrict__ Bh,
               const __half* __restrict__ A2h, const __half* __restrict__ B2h,
               const float* __restrict__ bias, const float* __restrict__ bias2,
               const __half* __restrict__ Cin_hi, const __half* __restrict__ Cin_lo,
               const __half* __restrict__ Uold,
               __half* __restrict__ Ohi, __half* __restrict__ Olo, __half* __restrict__ Ou,
               const int* __restrict__ gidx,
               const float* __restrict__ Xo, const float* __restrict__ Mo)
{
    constexpr int  NC     = KDIM / 64;
    constexpr bool GATHER = (MODE == MODE_RELU_G || MODE == MODE_RNN);

    extern __shared__ char smraw[];
    const uint32_t sbase = smem_u32(smraw);
    const uint32_t tbase = (sbase + 1023u) & ~1023u;
    char* ctrlp = smraw + (tbase - sbase) + NSTAGE * STAGE_BYTES;
    int*   sIdx = (int*)ctrlp;
    float* redL = (float*)(ctrlp + 512);
    float* redM = (float*)(ctrlp + 544);

    const int tid = threadIdx.x, wid = tid >> 5, lid = tid & 31;
    const int rowbase = blockIdx.y * 128;
    const int colbase = blockIdx.x * 128;
    const int wr = wid & 3, wc = wid >> 2;

    if (GATHER) {
        if (tid < 128) sIdx[tid] = gidx[rowbase + tid];
        __syncthreads();
    }

    auto load_chunk = [&](int kc, int stage) {
        const uint32_t sb = tbase + (uint32_t)stage * STAGE_BYTES;
#pragma unroll
        for (int u = 0; u < 8; u++) {
            const int mat = u >> 2;
            const int rem = (u & 3) * 256 + tid;
            const int row = rem >> 3;
            const int un  = rem & 7;
            const __half* src;
            if constexpr (MODE == MODE_RNN) {
                if (mat == 0) {
                    if (kc < 2) src = Ah  + (size_t)(rowbase + row) * DIN + kc * 64 + un * 8;
                    else        src = A2h + (size_t)sIdx[row] * HID + (kc - 2) * 64 + un * 8;
                } else {
                    if (kc < 2) src = Bh  + (size_t)(colbase + row) * DIN + kc * 64 + un * 8;
                    else        src = B2h + (size_t)(colbase + row) * HID + (kc - 2) * 64 + un * 8;
                }
            } else {
                if (mat == 0) {
                    int rg = GATHER ? sIdx[row] : (rowbase + row);
                    src = Ah + (size_t)rg * KDIM + kc * 64 + un * 8;
                } else {
                    src = Bh + (size_t)(colbase + row) * KDIM + kc * 64 + un * 8;
                }
            }
            cp16(sb + (uint32_t)mat * TILE_BYTES + sw128((uint32_t)(row * 128 + un * 16)), src);
        }
    };

    float acc[2][8][4];
#pragma unroll
    for (int i = 0; i < 2; i++)
#pragma unroll
        for (int j = 0; j < 8; j++)
#pragma unroll
            for (int q = 0; q < 4; q++) acc[i][j][q] = 0.f;

    auto compute = [&](int stage) {
        const uint32_t sb = tbase + (uint32_t)stage * STAGE_BYTES;
#pragma unroll
        for (int k16 = 0; k16 < 4; k16++) {
            uint32_t ah[2][4];
#pragma unroll
            for (int mi = 0; mi < 2; mi++) {
                uint32_t off = (uint32_t)((wr * 32 + mi * 16 + (lid & 15)) * 128
                                          + k16 * 32 + (lid >> 4) * 16);
                ldm4(ah[mi], sb + sw128(off));
            }
            uint32_t bh[4][4];
#pragma unroll
            for (int nb = 0; nb < 4; nb++) {
                uint32_t off = (uint32_t)((wc * 64 + nb * 16 + (lid & 7) + ((lid >> 4) & 1) * 8) * 128
                                          + k16 * 32 + ((lid >> 3) & 1) * 16);
                ldm4(bh[nb], sb + TILE_BYTES + sw128(off));
            }
#pragma unroll
            for (int mi = 0; mi < 2; mi++)
#pragma unroll
                for (int na = 0; na < 8; na++)
                    mma16816(acc[mi][na], ah[mi], &bh[na >> 1][(na & 1) * 2]);
        }
    };

    // single-sync multistage mainloop (R12)
    load_chunk(0, 0); cp_commit();
    load_chunk(1, 1); cp_commit();
#pragma unroll 1
    for (int c = 0; c < NC; c++) {
        if (c + 1 < NC) cp_wait<1>();
        else            cp_wait<0>();
        __syncthreads();
        if (c + 2 < NC) { load_chunk(c + 2, (c + 2) % NSTAGE); cp_commit(); }
        compute(c % NSTAGE);
    }

    float lsum = 0.f, msum = 0.f;
#pragma unroll
    for (int mi = 0; mi < 2; mi++) {
#pragma unroll
        for (int hh = 0; hh < 2; hh++) {
            const int row = rowbase + wr * 32 + mi * 16 + (lid >> 2) + hh * 8;
#pragma unroll
            for (int na = 0; na < 8; na++) {
                const int c = colbase + wc * 64 + na * 8 + (lid & 3) * 2;
                float v0 = acc[mi][na][hh * 2 + 0];
                float v1 = acc[mi][na][hh * 2 + 1];
                if constexpr (MODE == MODE_LOSS) {
                    float2 bb = *(const float2*)(bias + c);
                    float2 xx = *(const float2*)(Xo + (size_t)row * NOUT + c);
                    float2 mm = *(const float2*)(Mo + (size_t)row * NOUT + c);
                    lsum += fabsf(xx.x - (v0 + bb.x)) * mm.x + fabsf(xx.y - (v1 + bb.y)) * mm.y;
                    msum += mm.x + mm.y;
                } else if constexpr (MODE == MODE_ZSTEP) {
                    // v_out = u_old + tanh((z_hi+z_lo) + DT*(acc + cvec))
                    float2 cv = *(const float2*)(bias + c);
                    float2 zh = __half22float2(*(const __half2*)(Cin_hi + (size_t)row * NOUT + c));
                    float2 zl = __half22float2(*(const __half2*)(Cin_lo + (size_t)row * NOUT + c));
                    float2 uo = __half22float2(*(const __half2*)(Uold  + (size_t)row * NOUT + c));
                    float z0 = (zh.x + zl.x) + DTF * (v0 + cv.x);
                    float z1 = (zh.y + zl.y) + DTF * (v1 + cv.y);
                    float w0 = uo.x + tanhf(z0);
                    float w1 = uo.y + tanhf(z1);
                    *(__half2*)(Ohi + (size_t)row * NOUT + c) =
                        __halves2half2(__float2half_rn(w0), __float2half_rn(w1));
                } else if constexpr (MODE == MODE_HEULER) {
                    // h = (h_hi+h_lo) + DT*acc + 2*DT*bo2
                    float2 bb = *(const float2*)(bias + c);
                    float2 ch = __half22float2(*(const __half2*)(Cin_hi + (size_t)row * NOUT + c));
                    float2 cl = __half22float2(*(const __half2*)(Cin_lo + (size_t)row * NOUT + c));
                    float h0f = (ch.x + cl.x) + DTF * v0 + 2.f * DTF * bb.x;
                    float h1f = (ch.y + cl.y) + DTF * v1 + 2.f * DTF * bb.y;
                    __half h0 = __float2half_rn(h0f), h1 = __float2half_rn(h1f);
                    *(__half2*)(Ohi + (size_t)row * NOUT + c) = __halves2half2(h0, h1);
                    *(__half2*)(Olo + (size_t)row * NOUT + c) =
                        __halves2half2(__float2half_rn(h0f - __half2float(h0)),
                                       __float2half_rn(h1f - __half2float(h1)));
                } else if constexpr (MODE == MODE_ZNEW) {
                    // z = acc + bo1; u = tanh(z)
                    float2 bb = *(const float2*)(bias + c);
                    float z0 = v0 + bb.x, z1 = v1 + bb.y;
                    __half h0 = __float2half_rn(z0), h1 = __float2half_rn(z1);
                    *(__half2*)(Ohi + (size_t)row * NOUT + c) = __halves2half2(h0, h1);
                    *(__half2*)(Olo + (size_t)row * NOUT + c) =
                        __halves2half2(__float2half_rn(z0 - __half2float(h0)),
                                       __float2half_rn(z1 - __half2float(h1)));
                    *(__half2*)(Ou + (size_t)row * NOUT + c) =
                        __halves2half2(__float2half_rn(tanhf(z0)), __float2half_rn(tanhf(z1)));
                } else if constexpr (MODE == MODE_STOREH) {
                    *(__half2*)(Ohi + (size_t)row * NOUT + c) =
                        __halves2half2(__float2half_rn(v0), __float2half_rn(v1));
                } else {
                    if constexpr (MODE == MODE_RELU_G) {
                        float2 bb = *(const float2*)(bias + c);
                        v0 += bb.x; v1 += bb.y;
                        v0 = v0 > 0.f ? v0 : 0.f; v1 = v1 > 0.f ? v1 : 0.f;
                    } else if constexpr (MODE == MODE_RNN) {
                        float2 b1 = *(const float2*)(bias + c);
                        float2 b2 = *(const float2*)(bias2 + c);
                        v0 = tanhf(v0 + b1.x + b2.x);
                        v1 = tanhf(v1 + b1.y + b2.y);
                    }
                    __half h0 = __float2half_rn(v0);
                    __half h1 = __float2half_rn(v1);
                    *(__half2*)(Ohi + (size_t)row * NOUT + c) = __halves2half2(h0, h1);
                    if constexpr (MODE == MODE_RNN) {
                        __half l0 = __float2half_rn(v0 - __half2float(h0));
                        __half l1 = __float2half_rn(v1 - __half2float(h1));
                        *(__half2*)(Olo + (size_t)row * NOUT + c) = __halves2half2(l0, l1);
                    }
                }
            }
        }
    }

    if constexpr (MODE == MODE_LOSS) {
#pragma unroll
        for (int o = 16; o > 0; o >>= 1) {
            lsum += __shfl_xor_sync(0xFFFFFFFFu, lsum, o);
            msum += __shfl_xor_sync(0xFFFFFFFFu, msum, o);
        }
        if (lid == 0) { redL[wid] = lsum; redM[wid] = msum; }
        __syncthreads();
        if (tid == 0) {
            float L = 0.f, Mt = 0.f;
#pragma unroll
            for (int i = 0; i < 8; i++) { L += redL[i]; Mt += redM[i]; }
            atomicAdd(&g_loss, (double)L);
            atomicAdd(&g_totm, (double)Mt);
        }
    }
}

template<int MODE, int KDIM, int NOUT>
__global__ __launch_bounds__(256, 2)
void mma_gemm(const __half* __restrict__ Ah,  const __half* __restrict__ Bh,
              const __half* __restrict__ A2h, const __half* __restrict__ B2h,
              const float* __restrict__ bias, const float* __restrict__ bias2,
              const __half* __restrict__ Cin_hi, const __half* __restrict__ Cin_lo,
              const __half* __restrict__ Uold,
              __half* __restrict__ Ohi, __half* __restrict__ Olo, __half* __restrict__ Ou,
              const int* __restrict__ gidx,
              const float* __restrict__ Xo, const float* __restrict__ Mo)
{
    gemm_body<MODE, KDIM, NOUT>(Ah, Bh, A2h, B2h, bias, bias2, Cin_hi, Cin_lo,
                                Uold, Ohi, Olo, Ou, gidx, Xo, Mo);
}

// ------------------------------------------------------------------
// Small kernels
// ------------------------------------------------------------------
__global__ void zero_acc_kernel() { g_loss = 0.0; g_totm = 0.0; }

// column values for z/u init: z0 = bo1 (since h0 = 0)
__global__ void colvals_kernel(const float* __restrict__ bo1)
{
    int c = blockIdx.x * 256 + threadIdx.x;
    if (c < HID) {
        float z = bo1[c];
        __half zh = __float2half_rn(z);
        g_zch[c] = zh;
        g_zcl[c] = __float2half_rn(z - __half2float(zh));
        g_uc[c]  = __float2half_rn(tanhf(z));
    }
}

// per-row state init: h=0, z=bo1 split, u=tanh(bo1)
__global__ void init_state_kernel()
{
    int row = blockIdx.x;          // 0..NSAMP-1
    int t = threadIdx.x;           // 0..255
    size_t base = (size_t)row * HID;
#pragma unroll
    for (int q = 0; q < 2; q++) {
        int c = t + q * 256;
        g_h_hi[base + c] = __float2half_rn(0.f);
        g_h_lo[base + c] = __float2half_rn(0.f);
        g_z_hi[base + c] = g_zch[c];
        g_z_lo[base + c] = g_zcl[c];
        g_u  [base + c] = g_uc[c];
    }
}

__global__ void conv_hi_kernel(const float* __restrict__ src,
                               __half* __restrict__ hi, int n4)
{
    int i = blockIdx.x * blockDim.x + threadIdx.x;
    if (i >= n4) return;
    float4 s = ((const float4*)src)[i];
    ((__half2*)hi)[i * 2]     = __halves2half2(__float2half_rn(s.x), __float2half_rn(s.y));
    ((__half2*)hi)[i * 2 + 1] = __halves2half2(__float2half_rn(s.z), __float2half_rn(s.w));
}

__global__ void conv_weights_kernel(const float* __restrict__ W_ih, const float* __restrict__ W_hh,
                                    const float* __restrict__ Wo1,  const float* __restrict__ Wo2,
                                    const float* __restrict__ Wp1,  const float* __restrict__ Wp2)
{
    int i = blockIdx.x * blockDim.x + threadIdx.x;   // float4 index, total 294912
    const float* src; __half* dst; int base;
    if      (i <  16384) { src = W_ih; dst = g_Wih_h; base = 0;      }
    else if (i <  81920) { src = W_hh; dst = g_Whh_h; base = 16384;  }
    else if (i < 147456) { src = Wo1;  dst = g_Wo1_h; base = 81920;  }
    else if (i < 212992) { src = Wo2;  dst = g_Wo2_h; base = 147456; }
    else if (i < 278528) { src = Wp1;  dst = g_Wp1_h; base = 212992; }
    else if (i < 294912) { src = Wp2;  dst = g_Wp2_h; base = 278528; }
    else return;
    int j = i - base;
    float4 s = ((const float4*)src)[j];
    ((__half2*)dst)[j * 2]     = __halves2half2(__float2half_rn(s.x), __float2half_rn(s.y));
    ((__half2*)dst)[j * 2 + 1] = __halves2half2(__float2half_rn(s.z), __float2half_rn(s.w));
}

// Wo2T[i][j] = fp16(Wo2[j][i])
__global__ void transpose_conv_kernel(const float* __restrict__ Wo2)
{
    int i = blockIdx.x * blockDim.x + threadIdx.x;   // out index over HID*HID
    if (i >= HID * HID) return;
    int r = i >> 9, c = i & 511;
    g_Wo2T_h[i] = __float2half_rn(Wo2[c * HID + r]);
}

// cvec = bo2 @ Wo1^T  (fp32)
__global__ void cvec_kernel(const float* __restrict__ Wo1, const float* __restrict__ bo2)
{
    int n = blockIdx.x * 256 + threadIdx.x;
    if (n >= HID) return;
    float s = 0.f;
    const float* wr = Wo1 + (size_t)n * HID;
#pragma unroll 4
    for (int m = 0; m < HID; m++) s += wr[m] * bo2[m];
    g_cvec[n] = s;
}

__global__ void scatter_kernel(const int* __restrict__ idx)
{
    int r = blockIdx.x;                 // 0..EOBS-1
    int t = threadIdx.x;                // 0..127
    int dst = idx[r];
    if (t < 64) {
        ((uint4*)(g_h_hi + (size_t)dst * HID))[t] = ((const uint4*)(g_hn_hi + (size_t)r * HID))[t];
    } else {
        ((uint4*)(g_h_lo + (size_t)dst * HID))[t - 64] = ((const uint4*)(g_hn_lo + (size_t)r * HID))[t - 64];
    }
}

__global__ void final_kernel(float* __restrict__ out)
{
    out[0] = (float)g_loss;
    out[1] = (float)(g_loss / g_totm);
}

// ------------------------------------------------------------------
// Launch
// ------------------------------------------------------------------
extern "C" void kernel_launch(void* const* d_in, const int* in_sizes, int n_in,
                              void* d_out, int out_size)
{
    const float* X    = (const float*)d_in[0];
    const float* Mm   = (const float*)d_in[1];
    const int*   bidx = (const int*)  d_in[2];
    const float* W_ih = (const float*)d_in[3];
    const float* b_ih = (const float*)d_in[4];
    const float* W_hh = (const float*)d_in[5];
    const float* b_hh = (const float*)d_in[6];
    const float* Wo1  = (const float*)d_in[7];
    const float* bo1  = (const float*)d_in[8];
    const float* Wo2  = (const float*)d_in[9];
    const float* bo2  = (const float*)d_in[10];
    const float* Wp1  = (const float*)d_in[11];
    const float* bp1  = (const float*)d_in[12];
    const float* Wp2  = (const float*)d_in[13];
    const float* bp2  = (const float*)d_in[14];

    __half *h_hi, *h_lo, *z_hi, *z_lo, *u, *v, *p1_hi, *hn_hi, *hn_lo, *X_hi;
    __half *Wih, *Whh, *Wo1h, *Wo2h, *Wo2Th, *W21h, *Wp1h, *Wp2h;
    float* cvec;
    cudaGetSymbolAddress((void**)&h_hi,  g_h_hi);   cudaGetSymbolAddress((void**)&h_lo,  g_h_lo);
    cudaGetSymbolAddress((void**)&z_hi,  g_z_hi);   cudaGetSymbolAddress((void**)&z_lo,  g_z_lo);
    cudaGetSymbolAddress((void**)&u,     g_u);      cudaGetSymbolAddress((void**)&v,     g_v);
    cudaGetSymbolAddress((void**)&p1_hi, g_p1_hi);
    cudaGetSymbolAddress((void**)&hn_hi, g_hn_hi);  cudaGetSymbolAddress((void**)&hn_lo, g_hn_lo);
    cudaGetSymbolAddress((void**)&X_hi,  g_X_hi);
    cudaGetSymbolAddress((void**)&Wih,   g_Wih_h);
    cudaGetSymbolAddress((void**)&Whh,   g_Whh_h);
    cudaGetSymbolAddress((void**)&Wo1h,  g_Wo1_h);
    cudaGetSymbolAddress((void**)&Wo2h,  g_Wo2_h);
    cudaGetSymbolAddress((void**)&Wo2Th, g_Wo2T_h);
    cudaGetSymbolAddress((void**)&W21h,  g_W21_h);
    cudaGetSymbolAddress((void**)&Wp1h,  g_Wp1_h);
    cudaGetSymbolAddress((void**)&Wp2h,  g_Wp2_h);
    cudaGetSymbolAddress((void**)&cvec,  g_cvec);

    cudaFuncSetAttribute(mma_gemm<MODE_ZSTEP,  HID, HID>, cudaFuncAttributeMaxDynamicSharedMemorySize, SMEM_DYN);
    cudaFuncSetAttribute(mma_gemm<MODE_HEULER, HID, HID>, cudaFuncAttributeMaxDynamicSharedMemorySize, SMEM_DYN);
    cudaFuncSetAttribute(mma_gemm<MODE_ZNEW,   HID, HID>, cudaFuncAttributeMaxDynamicSharedMemorySize, SMEM_DYN);
    cudaFuncSetAttribute(mma_gemm<MODE_STOREH, HID, HID>, cudaFuncAttributeMaxDynamicSharedMemorySize, SMEM_DYN);
    cudaFuncSetAttribute(mma_gemm<MODE_RELU_G, HID, HID>, cudaFuncAttributeMaxDynamicSharedMemorySize, SMEM_DYN);
    cudaFuncSetAttribute(mma_gemm<MODE_LOSS,   HID, DIN>, cudaFuncAttributeMaxDynamicSharedMemorySize, SMEM_DYN);
    cudaFuncSetAttribute(mma_gemm<MODE_RNN,    640, HID>, cudaFuncAttributeMaxDynamicSharedMemorySize, SMEM_DYN);

    // ---- one-time setup (per graph replay) ----
    zero_acc_kernel<<<1, 1>>>();
    conv_hi_kernel<<<(KOBS*EOBS*DIN/4 + 255)/256, 256>>>(X, X_hi, KOBS*EOBS*DIN/4);
    conv_weights_kernel<<<1152, 256>>>(W_ih, W_hh, Wo1, Wo2, Wp1, Wp2);
    transpose_conv_kernel<<<(HID*HID + 255)/256, 256>>>(Wo2);
    // W21 = Wo1 @ Wo2  (A=Wo1h, B=Wo2T_h -> C[i,n] = sum_k Wo1[i,k]*Wo2[k,n])
    mma_gemm<MODE_STOREH, HID, HID><<<dim3(4, 4), 256, SMEM_DYN>>>(
        Wo1h, Wo2Th, nullptr, nullptr, nullptr, nullptr, nullptr, nullptr, nullptr,
        W21h, nullptr, nullptr, nullptr, nullptr, nullptr);
    cvec_kernel<<<2, 256>>>(Wo1, bo2);
    colvals_kernel<<<2, 256>>>(bo1);
    init_state_kernel<<<NSAMP, 256>>>();

    const dim3 gEuler(HID / 128, NSAMP / 128);  // (4, 128)
    const dim3 gObs  (HID / 128, EOBS  / 128);  // (4, 32)
    const dim3 gLoss (DIN / 128, EOBS  / 128);  // (1, 32)

    for (int s = 0; s < KOBS; s++) {
        const float* Xs = X  + (size_t)s * EOBS * DIN;
        const float* Ms = Mm + (size_t)s * EOBS * DIN;
        const int*   is = bidx + (size_t)s * EOBS;
        const __half* Xhs = X_hi + (size_t)s * EOBS * DIN;

        // v = u0 + tanh(z + DT*(u0 @ W21^T + cvec))       [both Euler tanh evals, 1 GEMM]
        mma_gemm<MODE_ZSTEP, HID, HID><<<gEuler, 256, SMEM_DYN>>>(
            u, W21h, nullptr, nullptr, cvec, nullptr, z_hi, z_lo, u,
            v, nullptr, nullptr, nullptr, nullptr, nullptr);
        // h = (h_hi+h_lo) + DT*(v @ Wo2^T) + 2*DT*bo2     [combined h update, 1 GEMM]
        mma_gemm<MODE_HEULER, HID, HID><<<gEuler, 256, SMEM_DYN>>>(
            v, Wo2h, nullptr, nullptr, bo2, nullptr, h_hi, h_lo, nullptr,
            h_hi, h_lo, nullptr, nullptr, nullptr, nullptr);
        // p1 = relu(h[idx] @ Wp1^T + bp1)
        mma_gemm<MODE_RELU_G, HID, HID><<<gObs, 256, SMEM_DYN>>>(
            h_hi, Wp1h, nullptr, nullptr, bp1, nullptr, nullptr, nullptr, nullptr,
            p1_hi, nullptr, nullptr, is, nullptr, nullptr);
        // loss += sum |X - (p1 @ Wp2^T + bp2)| * M ; totm += sum M
        mma_gemm<MODE_LOSS, HID, DIN><<<gLoss, 256, SMEM_DYN>>>(
            p1_hi, Wp2h, nullptr, nullptr, bp2, nullptr, nullptr, nullptr, nullptr,
            nullptr, nullptr, nullptr, nullptr, Xs, Ms);
        // hn = tanh([X | h[idx]] @ [Wih | Whh]^T + b_ih + b_hh)
        mma_gemm<MODE_RNN, 640, HID><<<gObs, 256, SMEM_DYN>>>(
            Xhs, Wih, h_hi, Whh, b_ih, b_hh, nullptr, nullptr, nullptr,
            hn_hi, hn_lo, nullptr, is, nullptr, nullptr);
        // h[idx] = hn
        scatter_kernel<<<EOBS, 128>>>(is);
        // z = h @ Wo1^T + bo1 ; u = tanh(z)   (refresh z-space state; skip on last step)
        if (s + 1 < KOBS) {
            mma_gemm<MODE_ZNEW, HID, HID><<<gEuler, 256, SMEM_DYN>>>(
                h_hi, Wo1h, nullptr, nullptr, bo1, nullptr, nullptr, nullptr, nullptr,
                z_hi, z_lo, u, nullptr, nullptr, nullptr);
        }
    }
    // prop_to_end Euler steps are output-invariant -> skipped.

    final_kernel<<<1, 1>>>((float*)d_out);
}

// round 15
// speedup vs baseline: 1.3796x; 1.3796x over previous
#include <cuda_runtime.h>
#include <cuda_fp16.h>
#include <cstdint>
#include <cstddef>

#define NSAMP 16384
#define HID   512
#define DIN   128
#define EOBS  4096
#define KOBS  40
#define DTF   0.05f

#define MODE_TANH    0
#define MODE_EULER   1
#define MODE_RELU_G  2
#define MODE_RNN     3
#define MODE_LOSS    5

// ------------------------------------------------------------------
// Device scratch (no allocations allowed)
// ------------------------------------------------------------------
__device__ __half g_h_hi[(size_t)NSAMP*HID];   // state hi
__device__ __half g_h_lo[(size_t)NSAMP*HID];   // state lo (precision carrier)
__device__ __half g_t_hi[(size_t)NSAMP*HID];
__device__ __half g_p1_hi[(size_t)EOBS*HID];
__device__ __half g_hn_hi[(size_t)EOBS*HID];
__device__ __half g_hn_lo[(size_t)EOBS*HID];
__device__ __half g_X_hi[(size_t)KOBS*EOBS*DIN];

__device__ __half g_Wih_h[HID*DIN];
__device__ __half g_Whh_h[HID*HID];
__device__ __half g_Wo1_h[HID*HID];
__device__ __half g_Wo2_h[HID*HID];
__device__ __half g_Wp1_h[HID*HID];
__device__ __half g_Wp2_h[DIN*HID];

__device__ double g_loss;
__device__ double g_totm;

// ------------------------------------------------------------------
// PTX helpers (portable sm_80+)
// ------------------------------------------------------------------
__device__ __forceinline__ uint32_t smem_u32(const void* p) {
    uint32_t a;
    asm("{ .reg .u64 t; cvta.to.shared.u64 t, %1; cvt.u32.u64 %0, t; }" : "=r"(a) : "l"(p));
    return a;
}
__device__ __forceinline__ void cp16(uint32_t dst, const void* src) {
    asm volatile("cp.async.cg.shared.global [%0], [%1], 16;" :: "r"(dst), "l"(src) : "memory");
}
__device__ __forceinline__ void cp_commit() {
    asm volatile("cp.async.commit_group;" ::: "memory");
}
template<int N>
__device__ __forceinline__ void cp_wait() {
    asm volatile("cp.async.wait_group %0;" :: "n"(N) : "memory");
}
__device__ __forceinline__ void ldm4(uint32_t* r, uint32_t addr) {
    asm volatile("ldmatrix.sync.aligned.m8n8.x4.shared.b16 {%0,%1,%2,%3}, [%4];"
                 : "=r"(r[0]), "=r"(r[1]), "=r"(r[2]), "=r"(r[3]) : "r"(addr));
}
__device__ __forceinline__ void mma16816(float* d, const uint32_t* a, const uint32_t* b) {
    asm volatile(
        "mma.sync.aligned.m16n8k16.row.col.f32.f16.f16.f32 "
        "{%0,%1,%2,%3}, {%4,%5,%6,%7}, {%8,%9}, {%0,%1,%2,%3};"
        : "+f"(d[0]), "+f"(d[1]), "+f"(d[2]), "+f"(d[3])
        : "r"(a[0]), "r"(a[1]), "r"(a[2]), "r"(a[3]), "r"(b[0]), "r"(b[1]));
}
__device__ __forceinline__ uint32_t sw128(uint32_t off) { return off ^ ((off >> 3) & 0x70); }

// SMEM plan: [pad <=1024][3 stages x 2 mats x 16KB][ctrl 1KB]
#define TILE_BYTES   16384
#define STAGE_BYTES  32768
#define NSTAGE       3
#define SMEM_DYN     (NSTAGE*STAGE_BYTES + 1024 + 1024)

// ------------------------------------------------------------------
// GEMM body: C[M,NOUT] = epi( A[M,K] @ W[NOUT,K]^T )   [R12 core, proven 34us]
// fp16 inputs, fp32 accumulators. CTA 128x128, 8 warps (4x2), warp tile 32x64.
// Single __syncthreads per K-chunk multistage (NSTAGE=3, race-free).
// MODE_RNN: K=640 concatenation  [X(128) | h_gathered(512)] @ [Wih | Whh]^T
// ------------------------------------------------------------------
template<int MODE, int KDIM, int NOUT>
__device__ __forceinline__
void gemm_body(const __half* __restrict__ Ah,  const __half* __restrict__ Bh,
               const __half* __restrict__ A2h, const __half* __restrict__ B2h,
               const float* __restrict__ bias, const float* __restrict__ bias2,
               const __half* __restrict__ Cin_hi, const __half* __restrict__ Cin_lo,
               __half* __restrict__ Ohi, __half* __restrict__ Olo,
               const int* __restrict__ gidx,
               const float* __restrict__ Xo, const float* __restrict__ Mo)
{
    constexpr int  NC     = KDIM / 64;
    constexpr bool GATHER = (MODE == MODE_RELU_G || MODE == MODE_RNN);

    extern __shared__ char smraw[];
    const uint32_t sbase = smem_u32(smraw);
    const uint32_t tbase = (sbase + 1023u) & ~1023u;
    char* ctrlp = smraw + (tbase - sbase) + NSTAGE * STAGE_BYTES;
    int*   sIdx = (int*)ctrlp;
    float* redL = (float*)(ctrlp + 512);
    float* redM = (float*)(ctrlp + 544);

    const int tid = threadIdx.x, wid = tid >> 5, lid = tid & 31;
    const int rowbase = blockIdx.y * 128;
    const int colbase = blockIdx.x * 128;
    const int wr = wid & 3, wc = wid >> 2;

    if (GATHER) {
        if (tid < 128) sIdx[tid] = gidx[rowbase + tid];
        __syncthreads();
    }

    auto load_chunk = [&](int kc, int stage) {
        const uint32_t sb = tbase + (uint32_t)stage * STAGE_BYTES;
#pragma unroll
        for (int u = 0; u < 8; u++) {
            const int mat = u >> 2;
            const int rem = (u & 3) * 256 + tid;
            const int row = rem >> 3;
            const int un  = rem & 7;
            const __half* src;
            if constexpr (MODE == MODE_RNN) {
                if (mat == 0) {
                    if (kc < 2) src = Ah  + (size_t)(rowbase + row) * DIN + kc * 64 + un * 8;
                    else        src = A2h + (size_t)sIdx[row] * HID + (kc - 2) * 64 + un * 8;
                } else {
                    if (kc < 2) src = Bh  + (size_t)(colbase + row) * DIN + kc * 64 + un * 8;
                    else        src = B2h + (size_t)(colbase + row) * HID + (kc - 2) * 64 + un * 8;
                }
            } else {
                if (mat == 0) {
                    int rg = GATHER ? sIdx[row] : (rowbase + row);
                    src = Ah + (size_t)rg * KDIM + kc * 64 + un * 8;
                } else {
                    src = Bh + (size_t)(colbase + row) * KDIM + kc * 64 + un * 8;
                }
            }
            cp16(sb + (uint32_t)mat * TILE_BYTES + sw128((uint32_t)(row * 128 + un * 16)), src);
        }
    };

    float acc[2][8][4];
#pragma unroll
    for (int i = 0; i < 2; i++)
#pragma unroll
        for (int j = 0; j < 8; j++)
#pragma unroll
            for (int q = 0; q < 4; q++) acc[i][j][q] = 0.f;

    auto compute = [&](int stage) {
        const uint32_t sb = tbase + (uint32_t)stage * STAGE_BYTES;
#pragma unroll
        for (int k16 = 0; k16 < 4; k16++) {
            uint32_t ah[2][4];
#pragma unroll
            for (int mi = 0; mi < 2; mi++) {
                uint32_t off = (uint32_t)((wr * 32 + mi * 16 + (lid & 15)) * 128
                                          + k16 * 32 + (lid >> 4) * 16);
                ldm4(ah[mi], sb + sw128(off));
            }
            uint32_t bh[4][4];
#pragma unroll
            for (int nb = 0; nb < 4; nb++) {
                uint32_t off = (uint32_t)((wc * 64 + nb * 16 + (lid & 7) + ((lid >> 4) & 1) * 8) * 128
                                          + k16 * 32 + ((lid >> 3) & 1) * 16);
                ldm4(bh[nb], sb + TILE_BYTES + sw128(off));
            }
#pragma unroll
            for (int mi = 0; mi < 2; mi++)
#pragma unroll
                for (int na = 0; na < 8; na++)
                    mma16816(acc[mi][na], ah[mi], &bh[na >> 1][(na & 1) * 2]);
        }
    };

    // single-sync multistage mainloop
    load_chunk(0, 0); cp_commit();
    load_chunk(1, 1); cp_commit();
#pragma unroll 1
    for (int c = 0; c < NC; c++) {
        if (c + 1 < NC) cp_wait<1>();
        else            cp_wait<0>();
        __syncthreads();
        if (c + 2 < NC) { load_chunk(c + 2, (c + 2) % NSTAGE); cp_commit(); }
        compute(c % NSTAGE);
    }

    float lsum = 0.f, msum = 0.f;
#pragma unroll
    for (int mi = 0; mi < 2; mi++) {
#pragma unroll
        for (int hh = 0; hh < 2; hh++) {
            const int row = rowbase + wr * 32 + mi * 16 + (lid >> 2) + hh * 8;
#pragma unroll
            for (int na = 0; na < 8; na++) {
                const int c = colbase + wc * 64 + na * 8 + (lid & 3) * 2;
                float v0 = acc[mi][na][hh * 2 + 0];
                float v1 = acc[mi][na][hh * 2 + 1];
                if constexpr (MODE == MODE_LOSS) {
                    float2 bb = *(const float2*)(bias + c);
                    float2 xx = *(const float2*)(Xo + (size_t)row * NOUT + c);
                    float2 mm = *(const float2*)(Mo + (size_t)row * NOUT + c);
                    lsum += fabsf(xx.x - (v0 + bb.x)) * mm.x + fabsf(xx.y - (v1 + bb.y)) * mm.y;
                    msum += mm.x + mm.y;
                } else {
                    if constexpr (MODE == MODE_TANH) {
                        float2 bb = *(const float2*)(bias + c);
                        v0 = tanhf(v0 + bb.x); v1 = tanhf(v1 + bb.y);
                    } else if constexpr (MODE == MODE_EULER) {
                        float2 bb = *(const float2*)(bias + c);
                        float2 chv = __half22float2(*(const __half2*)(Cin_hi + (size_t)row * NOUT + c));
                        float2 clv = __half22float2(*(const __half2*)(Cin_lo + (size_t)row * NOUT + c));
                        v0 = (chv.x + clv.x) + DTF * (v0 + bb.x);
                        v1 = (chv.y + clv.y) + DTF * (v1 + bb.y);
                    } else if constexpr (MODE == MODE_RELU_G) {
                        float2 bb = *(const float2*)(bias + c);
                        v0 += bb.x; v1 += bb.y;
                        v0 = v0 > 0.f ? v0 : 0.f; v1 = v1 > 0.f ? v1 : 0.f;
                    } else if constexpr (MODE == MODE_RNN) {
                        float2 b1 = *(const float2*)(bias + c);
                        float2 b2 = *(const float2*)(bias2 + c);
                        v0 = tanhf(v0 + b1.x + b2.x);
                        v1 = tanhf(v1 + b1.y + b2.y);
                    }
                    __half h0 = __float2half_rn(v0);
                    __half h1 = __float2half_rn(v1);
                    *(__half2*)(Ohi + (size_t)row * NOUT + c) = __halves2half2(h0, h1);
                    if constexpr (MODE == MODE_EULER || MODE == MODE_RNN) {
                        __half l0 = __float2half_rn(v0 - __half2float(h0));
                        __half l1 = __float2half_rn(v1 - __half2float(h1));
                        *(__half2*)(Olo + (size_t)row * NOUT + c) = __halves2half2(l0, l1);
                    }
                }
            }
        }
    }

    if constexpr (MODE == MODE_LOSS) {
#pragma unroll
        for (int o = 16; o > 0; o >>= 1) {
            lsum += __shfl_xor_sync(0xFFFFFFFFu, lsum, o);
            msum += __shfl_xor_sync(0xFFFFFFFFu, msum, o);
        }
        if (lid == 0) { redL[wid] = lsum; redM[wid] = msum; }
        __syncthreads();
        if (tid == 0) {
            float L = 0.f, Mt = 0.f;
#pragma unroll
            for (int i = 0; i < 8; i++) { L += redL[i]; Mt += redM[i]; }
            atomicAdd(&g_loss, (double)L);
            atomicAdd(&g_totm, (double)Mt);
        }
    }
}

// ---- thin wrappers for the serial Euler GEMMs ----
template<int MODE, int KDIM, int NOUT>
__global__ __launch_bounds__(256, 2)
void mma_gemm(const __half* __restrict__ Ah,  const __half* __restrict__ Bh,
              const float* __restrict__ bias,
              const __half* __restrict__ Cin_hi, const __half* __restrict__ Cin_lo,
              __half* __restrict__ Ohi, __half* __restrict__ Olo)
{
    gemm_body<MODE, KDIM, NOUT>(Ah, Bh, nullptr, nullptr, bias, nullptr,
                                Cin_hi, Cin_lo, Ohi, Olo, nullptr, nullptr, nullptr);
}

// ---- fused launch A: z=0 RELU_G, z=1 RNN (independent) ----
__global__ __launch_bounds__(256, 2)
void obs_a_kernel(const __half* __restrict__ h_hi,
                  const __half* __restrict__ Wp1h, const float* __restrict__ bp1,
                  __half* __restrict__ p1_hi,
                  const __half* __restrict__ Xhs,
                  const __half* __restrict__ Wih, const __half* __restrict__ Whh,
                  const float* __restrict__ b_ih, const float* __restrict__ b_hh,
                  __half* __restrict__ hn_hi, __half* __restrict__ hn_lo,
                  const int* __restrict__ is)
{
    if (blockIdx.z == 0)
        gemm_body<MODE_RELU_G, HID, HID>(h_hi, Wp1h, nullptr, nullptr, bp1, nullptr,
                                         nullptr, nullptr, p1_hi, nullptr, is, nullptr, nullptr);
    else
        gemm_body<MODE_RNN, 640, HID>(Xhs, Wih, h_hi, Whh, b_ih, b_hh,
                                      nullptr, nullptr, hn_hi, hn_lo, is, nullptr, nullptr);
}

// ---- fused launch B: z=0 LOSS (x==0 only), z=1 scatter (128 CTAs, full MLP) ----
__global__ __launch_bounds__(256, 2)
void obs_b_kernel(const __half* __restrict__ p1_hi,
                  const __half* __restrict__ Wp2h, const float* __restrict__ bp2,
                  const float* __restrict__ Xs, const float* __restrict__ Ms,
                  const int* __restrict__ is)
{
    if (blockIdx.z == 0) {
        if (blockIdx.x != 0) return;   // LOSS has a single col-tile (DIN=128)
        gemm_body<MODE_LOSS, HID, DIN>(p1_hi, Wp2h, nullptr, nullptr, bp2, nullptr,
                                       nullptr, nullptr, nullptr, nullptr, nullptr, Xs, Ms);
    } else {
        // scatter: 128 CTAs (x:4 * y:32), 32 rows each; 16 uint4 stores/thread
        const int tid = threadIdx.x;
        const int rowbase = (blockIdx.y * 4 + blockIdx.x) * 32;
#pragma unroll 1
        for (int i = tid; i < 32 * 64; i += 256) {
            int r = i >> 6, q = i & 63;
            size_t dst = (size_t)is[rowbase + r] * HID;
            size_t src = (size_t)(rowbase + r) * HID;
            ((uint4*)(g_h_hi + dst))[q] = ((const uint4*)(g_hn_hi + src))[q];
            ((uint4*)(g_h_lo + dst))[q] = ((const uint4*)(g_hn_lo + src))[q];
        }
    }
}

// ------------------------------------------------------------------
// Small kernels
// ------------------------------------------------------------------
__global__ void init_kernel()
{
    size_t i = (size_t)blockIdx.x * blockDim.x + threadIdx.x;   // over NSAMP*HID/8
    ((uint4*)g_h_hi)[i] = make_uint4(0, 0, 0, 0);
    ((uint4*)g_h_lo)[i] = make_uint4(0, 0, 0, 0);
    if (i == 0) { g_loss = 0.0; g_totm = 0.0; }
}

__global__ void conv_hi_kernel(const float* __restrict__ src,
                               __half* __restrict__ hi, int n4)
{
    int i = blockIdx.x * blockDim.x + threadIdx.x;
    if (i >= n4) return;
    float4 s = ((const float4*)src)[i];
    ((__half2*)hi)[i * 2]     = __halves2half2(__float2half_rn(s.x), __float2half_rn(s.y));
    ((__half2*)hi)[i * 2 + 1] = __halves2half2(__float2half_rn(s.z), __float2half_rn(s.w));
}

// all 6 weight conversions in ONE kernel
__global__ void conv_weights_kernel(const float* __restrict__ W_ih, const float* __restrict__ W_hh,
                                    const float* __restrict__ Wo1,  const float* __restrict__ Wo2,
                                    const float* __restrict__ Wp1,  const float* __restrict__ Wp2)
{
    int i = blockIdx.x * blockDim.x + threadIdx.x;   // float4 index, total 294912
    const float* src; __half* dst; int base;
    if      (i <  16384) { src = W_ih; dst = g_Wih_h; base = 0;      }
    else if (i <  81920) { src = W_hh; dst = g_Whh_h; base = 16384;  }
    else if (i < 147456) { src = Wo1;  dst = g_Wo1_h; base = 81920;  }
    else if (i < 212992) { src = Wo2;  dst = g_Wo2_h; base = 147456; }
    else if (i < 278528) { src = Wp1;  dst = g_Wp1_h; base = 212992; }
    else if (i < 294912) { src = Wp2;  dst = g_Wp2_h; base = 278528; }
    else return;
    int j = i - base;
    float4 s = ((const float4*)src)[j];
    ((__half2*)dst)[j * 2]     = __halves2half2(__float2half_rn(s.x), __float2half_rn(s.y));
    ((__half2*)dst)[j * 2 + 1] = __halves2half2(__float2half_rn(s.z), __float2half_rn(s.w));
}

__global__ void final_kernel(float* __restrict__ out)
{
    out[0] = (float)g_loss;
    out[1] = (float)(g_loss / g_totm);
}

// ------------------------------------------------------------------
// Launch
// ------------------------------------------------------------------
extern "C" void kernel_launch(void* const* d_in, const int* in_sizes, int n_in,
                              void* d_out, int out_size)
{
    const float* X    = (const float*)d_in[0];
    const float* Mm   = (const float*)d_in[1];
    const int*   bidx = (const int*)  d_in[2];
    const float* W_ih = (const float*)d_in[3];
    const float* b_ih = (const float*)d_in[4];
    const float* W_hh = (const float*)d_in[5];
    const float* b_hh = (const float*)d_in[6];
    const float* Wo1  = (const float*)d_in[7];
    const float* bo1  = (const float*)d_in[8];
    const float* Wo2  = (const float*)d_in[9];
    const float* bo2  = (const float*)d_in[10];
    const float* Wp1  = (const float*)d_in[11];
    const float* bp1  = (const float*)d_in[12];
    const float* Wp2  = (const float*)d_in[13];
    const float* bp2  = (const float*)d_in[14];

    __half *h_hi, *h_lo, *t_hi, *p1_hi, *hn_hi, *hn_lo, *X_hi;
    __half *Wih, *Whh, *Wo1h, *Wo2h, *Wp1h, *Wp2h;
    cudaGetSymbolAddress((void**)&h_hi,  g_h_hi);   cudaGetSymbolAddress((void**)&h_lo,  g_h_lo);
    cudaGetSymbolAddress((void**)&t_hi,  g_t_hi);
    cudaGetSymbolAddress((void**)&p1_hi, g_p1_hi);
    cudaGetSymbolAddress((void**)&hn_hi, g_hn_hi);  cudaGetSymbolAddress((void**)&hn_lo, g_hn_lo);
    cudaGetSymbolAddress((void**)&X_hi,  g_X_hi);
    cudaGetSymbolAddress((void**)&Wih,  g_Wih_h);
    cudaGetSymbolAddress((void**)&Whh,  g_Whh_h);
    cudaGetSymbolAddress((void**)&Wo1h, g_Wo1_h);
    cudaGetSymbolAddress((void**)&Wo2h, g_Wo2_h);
    cudaGetSymbolAddress((void**)&Wp1h, g_Wp1_h);
    cudaGetSymbolAddress((void**)&Wp2h, g_Wp2_h);

    cudaFuncSetAttribute(mma_gemm<MODE_TANH,   HID, HID>, cudaFuncAttributeMaxDynamicSharedMemorySize, SMEM_DYN);
    cudaFuncSetAttribute(mma_gemm<MODE_EULER,  HID, HID>, cudaFuncAttributeMaxDynamicSharedMemorySize, SMEM_DYN);
    cudaFuncSetAttribute(obs_a_kernel, cudaFuncAttributeMaxDynamicSharedMemorySize, SMEM_DYN);
    cudaFuncSetAttribute(obs_b_kernel, cudaFuncAttributeMaxDynamicSharedMemorySize, SMEM_DYN);

    // launch 0: zero state + accumulators
    init_kernel<<<(NSAMP * HID / 8) / 256, 256>>>();
    // launch 1: convert X
    conv_hi_kernel<<<(KOBS*EOBS*DIN/4 + 255)/256, 256>>>(X, X_hi, KOBS*EOBS*DIN/4);
    // launch 2: convert all 6 weight matrices
    conv_weights_kernel<<<1152, 256>>>(W_ih, W_hh, Wo1, Wo2, Wp1, Wp2);

    const dim3 gEuler(HID / 128, NSAMP / 128);      // (4, 128)
    const dim3 gObsA (HID / 128, EOBS  / 128, 2);   // (4, 32, 2): RELU_G || RNN
    const dim3 gObsB (4,         EOBS  / 128, 2);   // (4, 32, 2): LOSS(x==0) || scatter(4-way)

    for (int s = 0; s < KOBS; s++) {
        const float* Xs = X  + (size_t)s * EOBS * DIN;
        const float* Ms = Mm + (size_t)s * EOBS * DIN;
        const int*   is = bidx + (size_t)s * EOBS;
        const __half* Xhs = X_hi + (size_t)s * EOBS * DIN;

        for (int e = 0; e < 2; e++) {
            // t = tanh(h_hi @ Wo1^T + bo1)    (launch 5 in step 0 -> ncu lands here)
            mma_gemm<MODE_TANH, HID, HID><<<gEuler, 256, SMEM_DYN>>>(
                h_hi, Wo1h, bo1, nullptr, nullptr, t_hi, nullptr);
            // h = (h_hi+h_lo) + DT*(t @ Wo2^T + bo2)   (state kept hi+lo)
            mma_gemm<MODE_EULER, HID, HID><<<gEuler, 256, SMEM_DYN>>>(
                t_hi, Wo2h, bo2, h_hi, h_lo, h_hi, h_lo);
        }
        // RELU_G || RNN  (independent; both read h, write p1 / hn)
        obs_a_kernel<<<gObsA, 256, SMEM_DYN>>>(
            h_hi, Wp1h, bp1, p1_hi, Xhs, Wih, Whh, b_ih, b_hh, hn_hi, hn_lo, is);
        // LOSS || scatter  (independent; scatter legal: RNN finished last launch)
        obs_b_kernel<<<gObsB, 256, SMEM_DYN>>>(p1_hi, Wp2h, bp2, Xs, Ms, is);
    }
    // prop_to_end Euler steps are output-invariant -> skipped.

    final_kernel<<<1, 1>>>((float*)d_out);
}